// round 5
// baseline (speedup 1.0000x reference)
#include <cuda_runtime.h>
#include <cuda_bf16.h>

#define B_SIZE 16384
#define K_NEG  20
#define DIM    128

__global__ void zero_out_kernel(float* out, int n) {
    for (int i = threadIdx.x; i < n; i += blockDim.x) out[i] = 0.0f;
}

__device__ __forceinline__ float warp_sum(float v) {
    v += __shfl_xor_sync(0xffffffffu, v, 16);
    v += __shfl_xor_sync(0xffffffffu, v, 8);
    v += __shfl_xor_sync(0xffffffffu, v, 4);
    v += __shfl_xor_sync(0xffffffffu, v, 2);
    v += __shfl_xor_sync(0xffffffffu, v, 1);
    return v;
}

// Fast, stable log(sigmoid(x)) = min(x,0) - log(1 + exp(-|x|))
__device__ __forceinline__ float log_sigmoid_fast(float x) {
    return fminf(x, 0.0f) - __logf(1.0f + __expf(-fabsf(x)));
}

// Packed butterfly transpose-reduce over v[0..31]: after 5 stages, v[0] on
// lane L holds the fully lane-summed value of slot L. 31 shuffles total.
// Values never mix across slots — they are routed, so only slots 0..20 matter.
__device__ __forceinline__ float butterfly_reduce(float (&v)[32], int lane) {
    #pragma unroll
    for (int i = 0; i < 5; i++) {
        const int off = 1 << i;
        const bool par = (lane >> i) & 1;
        const int n = 32 >> i;
        #pragma unroll
        for (int j = 0; j < n / 2; j++) {
            const float a = v[2 * j];
            const float c = v[2 * j + 1];
            const float send = par ? a : c;
            const float keep = par ? c : a;
            const float got = __shfl_xor_sync(0xffffffffu, send, off);
            v[j] = keep + got;
        }
    }
    return v[0];
}

__global__ __launch_bounds__(128, 6) void skipgram_kernel(
    const int* __restrict__ target,
    const int* __restrict__ context,
    const int* __restrict__ negs,
    const float* __restrict__ in_embed,
    const float* __restrict__ out_embed,
    float* __restrict__ out)
{
    const int lane = threadIdx.x & 31;
    const int warp_in_block = threadIdx.x >> 5;
    // Each warp handles TWO batch rows: grid 2048 * 4 warps * 2 rows = 16384.
    const int bp = blockIdx.x * 4 + warp_in_block;
    const int b0 = bp * 2;
    const int b1 = b0 + 1;

    // One coalesced index load per row for the whole warp:
    // lane 0..19 -> neg index k=lane ; lane >= 20 -> context index.
    const int idx0 = (lane < K_NEG) ? __ldg(negs + (size_t)b0 * K_NEG + lane)
                                    : __ldg(context + b0);
    const int idx1 = (lane < K_NEG) ? __ldg(negs + (size_t)b1 * K_NEG + lane)
                                    : __ldg(context + b1);

    const float4 tv0 = reinterpret_cast<const float4*>(
        in_embed + (size_t)__ldg(target + b0) * DIM)[lane];
    const float4 tv1 = reinterpret_cast<const float4*>(
        in_embed + (size_t)__ldg(target + b1) * DIM)[lane];

    float v0[32], v1[32];
    #pragma unroll
    for (int j = K_NEG + 1; j < 32; j++) { v0[j] = 0.0f; v1[j] = 0.0f; }

    // Interleave the two rows' 42 independent gathers so loads for row 1 are
    // in flight while row 0's butterfly runs.
    #pragma unroll
    for (int k = 0; k <= K_NEG; k++) {
        const int r0 = __shfl_sync(0xffffffffu, idx0, k);
        const int r1 = __shfl_sync(0xffffffffu, idx1, k);
        const float4 a = reinterpret_cast<const float4*>(
            out_embed + (size_t)r0 * DIM)[lane];
        const float4 c = reinterpret_cast<const float4*>(
            out_embed + (size_t)r1 * DIM)[lane];
        v0[k] = tv0.x * a.x + tv0.y * a.y + tv0.z * a.z + tv0.w * a.w;
        v1[k] = tv1.x * c.x + tv1.y * c.y + tv1.z * c.z + tv1.w * c.w;
    }

    const float s0 = butterfly_reduce(v0, lane);
    const float s1 = butterfly_reduce(v1, lane);

    float contrib = 0.0f;
    if (lane <= K_NEG) {
        const float x0 = (lane == K_NEG) ? s0 : -s0;
        const float x1 = (lane == K_NEG) ? s1 : -s1;
        contrib = log_sigmoid_fast(x0) + log_sigmoid_fast(x1);
    }

    contrib = warp_sum(contrib);

    __shared__ float smem[4];
    if (lane == 0) smem[warp_in_block] = contrib;
    __syncthreads();

    if (threadIdx.x == 0) {
        float acc = smem[0] + smem[1] + smem[2] + smem[3];
        atomicAdd(out, -acc * (1.0f / (float)B_SIZE));
    }
}

extern "C" void kernel_launch(void* const* d_in, const int* in_sizes, int n_in,
                              void* d_out, int out_size) {
    const int*   target    = (const int*)d_in[0];
    const int*   context   = (const int*)d_in[1];
    const int*   negs      = (const int*)d_in[2];
    const float* in_embed  = (const float*)d_in[3];
    const float* out_embed = (const float*)d_in[4];
    float*       out       = (float*)d_out;

    zero_out_kernel<<<1, 32>>>(out, out_size);

    // 4 warps per block, two rows per warp: 16384 / 8 = 2048 blocks exact.
    skipgram_kernel<<<B_SIZE / 8, 128>>>(
        target, context, negs, in_embed, out_embed, out);
}

// round 6
// speedup vs baseline: 1.0222x; 1.0222x over previous
#include <cuda_runtime.h>
#include <cuda_bf16.h>

#define B_SIZE 16384
#define K_NEG  20
#define DIM    128

__global__ void zero_out_kernel(float* out, int n) {
    for (int i = threadIdx.x; i < n; i += blockDim.x) out[i] = 0.0f;
}

__device__ __forceinline__ float warp_sum(float v) {
    v += __shfl_xor_sync(0xffffffffu, v, 16);
    v += __shfl_xor_sync(0xffffffffu, v, 8);
    v += __shfl_xor_sync(0xffffffffu, v, 4);
    v += __shfl_xor_sync(0xffffffffu, v, 2);
    v += __shfl_xor_sync(0xffffffffu, v, 1);
    return v;
}

// Fast, stable log(sigmoid(x)) = min(x,0) - log(1 + exp(-|x|))
__device__ __forceinline__ float log_sigmoid_fast(float x) {
    return fminf(x, 0.0f) - __logf(1.0f + __expf(-fabsf(x)));
}

__global__ __launch_bounds__(128, 12) void skipgram_kernel(
    const int* __restrict__ target,
    const int* __restrict__ context,
    const int* __restrict__ negs,
    const float* __restrict__ in_embed,
    const float* __restrict__ out_embed,
    float* __restrict__ out)
{
    const int lane = threadIdx.x & 31;
    const int warp_in_block = threadIdx.x >> 5;
    // grid is exact: 16384 rows / (4 warps/block) = 4096 blocks, no bounds check.
    const int b = blockIdx.x * 4 + warp_in_block;

    // One coalesced index load for the whole warp:
    // lane 0..19 -> neg index k=lane ; lane 20..31 -> context index (uniform).
    const int* nb = negs + (size_t)b * K_NEG;
    const int idx = (lane < K_NEG) ? __ldg(nb + lane) : __ldg(context + b);

    // Each lane owns 4 consecutive floats of the 128-float row.
    const float4 tv = reinterpret_cast<const float4*>(
        in_embed + (size_t)__ldg(target + b) * DIM)[lane];

    // v[k] = this lane's partial dot for value k.
    // k in [0,20): negative scores; k == 20: positive; k > 20: don't-care.
    float v[32];

    #pragma unroll
    for (int k = 0; k <= K_NEG; k++) {
        const int row = __shfl_sync(0xffffffffu, idx, k);
        const float4 nv = reinterpret_cast<const float4*>(
            out_embed + (size_t)row * DIM)[lane];
        v[k] = tv.x * nv.x + tv.y * nv.y + tv.z * nv.z + tv.w * nv.w;
    }
    #pragma unroll
    for (int j = K_NEG + 1; j < 32; j++) v[j] = v[K_NEG];  // cheap pad (reg copy)

    // Packed butterfly transpose-reduce: after 5 stages, v[0] on lane L holds
    // the fully lane-summed score for value L. 31 shuffles total.
    #pragma unroll
    for (int i = 0; i < 5; i++) {
        const int off = 1 << i;
        const bool par = (lane >> i) & 1;
        const int n = 32 >> i;
        #pragma unroll
        for (int j = 0; j < n / 2; j++) {
            const float a = v[2 * j];
            const float c = v[2 * j + 1];
            const float send = par ? a : c;
            const float keep = par ? c : a;
            const float got = __shfl_xor_sync(0xffffffffu, send, off);
            v[j] = keep + got;
        }
    }

    const float s = v[0];                    // score for value index == lane
    const float x = (lane == K_NEG) ? s : -s;
    float contrib = (lane <= K_NEG) ? log_sigmoid_fast(x) : 0.0f;

    // Sum the 21 per-lane loss terms of this row, then block-reduce.
    contrib = warp_sum(contrib);

    __shared__ float smem[4];
    if (lane == 0) smem[warp_in_block] = contrib;
    __syncthreads();

    if (threadIdx.x == 0) {
        float acc = smem[0] + smem[1] + smem[2] + smem[3];
        atomicAdd(out, -acc * (1.0f / (float)B_SIZE));
    }
}

extern "C" void kernel_launch(void* const* d_in, const int* in_sizes, int n_in,
                              void* d_out, int out_size) {
    const int*   target    = (const int*)d_in[0];
    const int*   context   = (const int*)d_in[1];
    const int*   negs      = (const int*)d_in[2];
    const float* in_embed  = (const float*)d_in[3];
    const float* out_embed = (const float*)d_in[4];
    float*       out       = (float*)d_out;

    zero_out_kernel<<<1, 32>>>(out, out_size);

    // 4 warps per block, one batch row per warp; 16384/4 = 4096 blocks exact.
    skipgram_kernel<<<B_SIZE / 4, 128>>>(
        target, context, negs, in_embed, out_embed, out);
}